// round 12
// baseline (speedup 1.0000x reference)
#include <cuda_runtime.h>
#include <cuda_fp16.h>
#include <cstdint>

// ---------------- problem constants ----------------
static constexpr int E_  = 8;
static constexpr int H_  = 1024;
static constexpr int F_  = 4096;
static constexpr int T_  = 16384;
static constexpr int TPE_ = T_ / E_;   // 2048 tokens per expert

// ---------------- GEMM tile config ----------------
static constexpr int MT = 256;     // M tile
static constexpr int NT = 128;     // N tile
static constexpr int KC = 64;      // K chunk (fp16) = one 128B SW128 row-block
static constexpr int A_BYTES = MT * 128;          // 32768
static constexpr int B_BYTES = NT * 128;          // 16384
static constexpr int OFF_A = 0;
static constexpr int OFF_B = A_BYTES;
static constexpr int STAGE_BYTES = A_BYTES + B_BYTES;   // 49152
static constexpr int NSTAGE = 4;
static constexpr int SMEM_TOTAL = NSTAGE * STAGE_BYTES; // 196608
static constexpr int NTHREADS = 256;   // 8 warps

// ---------------- scratch (static device globals; no allocation) ----------------
__device__ __half g_xq[(size_t)T_ * H_];
__device__ __half g_w1q[(size_t)E_ * F_ * H_];   // transposed: [E][F][H]
__device__ __half g_w2q[(size_t)E_ * H_ * F_];   // transposed: [E][H][F]
__device__ __half g_iq[(size_t)T_ * F_];         // gelu(intermediate), fp16

#define DI __device__ __forceinline__

DI uint32_t smem_u32(const void* p) {
    uint32_t a;
    asm("{ .reg .u64 t; cvta.to.shared.u64 t, %1; cvt.u32.u64 %0, t; }"
        : "=r"(a) : "l"(p));
    return a;
}

DI float gelu_tanh(float x) {  // jax.nn.gelu default (approximate=True)
    float x3 = x * x * x;
    float t = tanhf(0.7978845608028654f * (x + 0.044715f * x3));
    return 0.5f * x * (1.0f + t);
}

// =================== tensor helpers (base ISA) ===================
#define LDSM_X4(r, addr)                                                           \
    asm volatile("ldmatrix.sync.aligned.m8n8.x4.shared.b16 {%0, %1, %2, %3}, [%4];" \
        : "=r"((r)[0]), "=r"((r)[1]), "=r"((r)[2]), "=r"((r)[3]) : "r"(addr))

DI void mma16816(float* c, const uint32_t* a, const uint32_t* b) {
    asm volatile(
        "mma.sync.aligned.m16n8k16.row.col.f32.f16.f16.f32 "
        "{%0, %1, %2, %3}, {%4, %5, %6, %7}, {%8, %9}, {%0, %1, %2, %3};"
        : "+f"(c[0]), "+f"(c[1]), "+f"(c[2]), "+f"(c[3])
        : "r"(a[0]), "r"(a[1]), "r"(a[2]), "r"(a[3]), "r"(b[0]), "r"(b[1]));
}

DI void cpasync16(uint32_t saddr, const void* gptr) {
    asm volatile("cp.async.cg.shared.global [%0], [%1], 16;"
                 :: "r"(saddr), "l"(gptr) : "memory");
}
#define CP_COMMIT() asm volatile("cp.async.commit_group;" ::: "memory")
#define CP_WAIT2()  asm volatile("cp.async.wait_group 2;" ::: "memory")

// async stage loader: A 256x128B + B 128x128B, SW128-swizzled
DI void load_stage_async(uint32_t stg_u,
                         const __half* __restrict__ A, const __half* __restrict__ B,
                         size_t arow0, size_t brow0, int K, size_t kb, int tid) {
#pragma unroll
    for (int v = tid; v < MT * 8; v += NTHREADS) {
        int r = v >> 3, cc = v & 7;
        size_t gb = ((arow0 + r) * (size_t)K + kb) * 2 + (size_t)cc * 16;
        uint32_t so = (uint32_t)(r * 128 + cc * 16);
        so ^= (so >> 3) & 0x70;
        cpasync16(stg_u + OFF_A + so, (const char*)A + gb);
    }
#pragma unroll
    for (int v = tid; v < NT * 8; v += NTHREADS) {
        int r = v >> 3, cc = v & 7;
        size_t gb = ((brow0 + r) * (size_t)K + kb) * 2 + (size_t)cc * 16;
        uint32_t so = (uint32_t)(r * 128 + cc * 16);
        so ^= (so >> 3) & 0x70;
        cpasync16(stg_u + OFF_B + so, (const char*)B + gb);
    }
}

// ---------------- prep kernels ----------------
// fp32 -> fp16 elementwise, vectorized x4
__global__ void k_cvt(const float4* __restrict__ in, __half2* __restrict__ o, int n4) {
    int i = blockIdx.x * blockDim.x + threadIdx.x;
    if (i >= n4) return;
    float4 v = in[i];
    o[2 * i]     = __floats2half2_rn(v.x, v.y);
    o[2 * i + 1] = __floats2half2_rn(v.z, v.w);
}

// per-expert transpose [R,C] -> [C,R] with fp32->fp16 conversion
__global__ void k_transpose_cvt(const float* __restrict__ in, __half* __restrict__ o,
                                int R, int C) {
    __shared__ float tile[32][33];
    size_t base = (size_t)blockIdx.z * R * C;
    int r0 = blockIdx.y * 32, c0 = blockIdx.x * 32;
    int tx = threadIdx.x, ty = threadIdx.y;
#pragma unroll
    for (int i = ty; i < 32; i += 8)
        tile[i][tx] = in[base + (size_t)(r0 + i) * C + c0 + tx];
    __syncthreads();
#pragma unroll
    for (int i = ty; i < 32; i += 8) {
        float v = tile[tx][i];
        size_t oo = base + (size_t)(c0 + i) * R + r0 + tx;
        o[oo] = __float2half_rn(v);
    }
}

// ---------------- grouped fp16 GEMM (single product, fp32 accum) ----------------
// CTA tile 256x128; 8 warps in 4(M)x2(N) grid of 64x64 warp tiles.
// A: [E*rowsA_pe, K] K-major fp16.  B: [E*rowsB_pe, K] K-major fp16.
// GELU_SPLIT: apply tanh-gelu, emit fp16 (GEMM1); else emit fp32 (GEMM2).
template <bool GELU_SPLIT>
__global__ void __launch_bounds__(NTHREADS, 1)
k_gemm(const __half* __restrict__ A, const __half* __restrict__ B,
       int K, int rowsA_pe, int rowsB_pe,
       __half* __restrict__ Oh, float* __restrict__ Of, int ldo) {
    extern __shared__ char smem[];
    uint32_t sb = smem_u32(smem);
    int tid = threadIdx.x, wid = tid >> 5, lid = tid & 31;

    size_t arow0 = (size_t)blockIdx.z * rowsA_pe + (size_t)blockIdx.y * MT;
    size_t brow0 = (size_t)blockIdx.z * rowsB_pe + (size_t)blockIdx.x * NT;
    size_t ncol0 = (size_t)blockIdx.x * NT;
    const int NC = K / KC;

    // warp tile: 64(M) x 64(N); mt 0..3 (m16), nt 0..7 (n8), np 0..3 (B n16 pairs)
    int m_off = (wid & 3) * 64;
    int n_off = (wid >> 2) * 64;
    uint32_t xorv = (uint32_t)(lid & 7) << 4;            // SW128 per-row XOR
    uint32_t a_row = (lid & 7) + ((lid >> 3) & 1) * 8;   // ldmatrix row-provider map
    uint32_t a_kx  = (uint32_t)(lid >> 4) * 16;          // k-byte half (0/16)
    uint32_t b_row = (lid & 7) + ((lid >> 4) & 1) * 8;
    uint32_t b_kx  = ((uint32_t)(lid >> 3) & 1) * 16;

    float acc[4][8][4];
#pragma unroll
    for (int mt = 0; mt < 4; ++mt)
#pragma unroll
        for (int nt = 0; nt < 8; ++nt)
#pragma unroll
            for (int r = 0; r < 4; ++r) acc[mt][nt][r] = 0.0f;

    // prologue: stages 0,1,2 in flight
    load_stage_async(sb, A, B, arow0, brow0, K, 0, tid);
    CP_COMMIT();
    load_stage_async(sb + STAGE_BYTES, A, B, arow0, brow0, K, KC, tid);
    CP_COMMIT();
    load_stage_async(sb + 2 * STAGE_BYTES, A, B, arow0, brow0, K, 2 * KC, tid);
    CP_COMMIT();

    for (int c = 0; c < NC; ++c) {
        CP_WAIT2();          // stage c landed (<=2 younger groups pending)
        __syncthreads();     // stage-c visible to all; buffer (c+3)%4 free (c-1 done)
        if (c + 3 < NC)
            load_stage_async(sb + ((c + 3) % NSTAGE) * STAGE_BYTES,
                             A, B, arow0, brow0, K, (size_t)(c + 3) * KC, tid);
        CP_COMMIT();         // commit every iter to keep group count stable

        uint32_t stg_u = sb + (c % NSTAGE) * STAGE_BYTES;
#pragma unroll
        for (int ks = 0; ks < KC / 16; ++ks) {
            uint32_t kin = (uint32_t)ks * 32;
            uint32_t av[4][4], bv[8][2];
#pragma unroll
            for (int mt = 0; mt < 4; ++mt) {
                uint32_t r = m_off + mt * 16 + a_row;
                uint32_t addr = stg_u + OFF_A + (r << 7) + ((kin + a_kx) ^ xorv);
                LDSM_X4(av[mt], addr);
            }
#pragma unroll
            for (int np = 0; np < 4; ++np) {
                uint32_t r = n_off + np * 16 + b_row;
                uint32_t addr = stg_u + OFF_B + (r << 7) + ((kin + b_kx) ^ xorv);
                uint32_t t0[4];
                LDSM_X4(t0, addr);
                bv[np * 2][0] = t0[0]; bv[np * 2][1] = t0[1];
                bv[np * 2 + 1][0] = t0[2]; bv[np * 2 + 1][1] = t0[3];
            }
#pragma unroll
            for (int mt = 0; mt < 4; ++mt)
#pragma unroll
                for (int nt = 0; nt < 8; ++nt)
                    mma16816(acc[mt][nt], av[mt], bv[nt]);
        }
    }

    // epilogue: thread holds D[g][2t..2t+1] (c0,c1) and D[g+8][2t..2t+1] (c2,c3)
    int g = lid >> 2, t2 = (lid & 3) * 2;
#pragma unroll
    for (int mt = 0; mt < 4; ++mt) {
#pragma unroll
        for (int nt = 0; nt < 8; ++nt) {
            size_t col = ncol0 + n_off + nt * 8 + t2;
            size_t row0 = arow0 + m_off + mt * 16 + g;
            size_t row1 = row0 + 8;
            float c0 = acc[mt][nt][0], c1 = acc[mt][nt][1];
            float c2 = acc[mt][nt][2], c3 = acc[mt][nt][3];
            if (GELU_SPLIT) {
                __half2 p0 = __floats2half2_rn(gelu_tanh(c0), gelu_tanh(c1));
                __half2 p1 = __floats2half2_rn(gelu_tanh(c2), gelu_tanh(c3));
                *(__half2*)(Oh + row0 * (size_t)ldo + col) = p0;
                *(__half2*)(Oh + row1 * (size_t)ldo + col) = p1;
            } else {
                *(float2*)(Of + row0 * (size_t)ldo + col) = make_float2(c0, c1);
                *(float2*)(Of + row1 * (size_t)ldo + col) = make_float2(c2, c3);
            }
        }
    }
}

// ---------------- launch ----------------
extern "C" void kernel_launch(void* const* d_in, const int* in_sizes, int n_in,
                              void* d_out, int out_size) {
    (void)in_sizes; (void)n_in; (void)out_size;
    const float* x  = (const float*)d_in[0];
    const float* w1 = (const float*)d_in[1];   // [E, H, F]
    const float* w2 = (const float*)d_in[2];   // [E, F, H]
    float* out = (float*)d_out;                // [T, H]

    __half *xq, *w1q, *w2q, *iq;
    cudaGetSymbolAddress((void**)&xq,  g_xq);
    cudaGetSymbolAddress((void**)&w1q, g_w1q);
    cudaGetSymbolAddress((void**)&w2q, g_w2q);
    cudaGetSymbolAddress((void**)&iq,  g_iq);

    // prep: convert x; transpose+convert weights to K-major B operands
    int n4 = T_ * H_ / 4;
    k_cvt<<<(n4 + 255) / 256, 256>>>((const float4*)x, (__half2*)xq, n4);
    dim3 tb(32, 8);
    k_transpose_cvt<<<dim3(F_ / 32, H_ / 32, E_), tb>>>(w1, w1q, H_, F_); // -> [E,F,H]
    k_transpose_cvt<<<dim3(H_ / 32, F_ / 32, E_), tb>>>(w2, w2q, F_, H_); // -> [E,H,F]

    cudaFuncSetAttribute(k_gemm<true>,  cudaFuncAttributeMaxDynamicSharedMemorySize, SMEM_TOTAL);
    cudaFuncSetAttribute(k_gemm<false>, cudaFuncAttributeMaxDynamicSharedMemorySize, SMEM_TOTAL);

    // GEMM1: I = gelu(X @ W1) -> fp16, [T, F]
    k_gemm<true><<<dim3(F_ / NT, TPE_ / MT, E_), NTHREADS, SMEM_TOTAL>>>(
        xq, w1q, H_, TPE_, F_, iq, nullptr, F_);
    // GEMM2: out = I @ W2 -> fp32, [T, H]
    k_gemm<false><<<dim3(H_ / NT, TPE_ / MT, E_), NTHREADS, SMEM_TOTAL>>>(
        iq, w2q, F_, TPE_, H_, nullptr, out, H_);
}

// round 13
// speedup vs baseline: 1.1022x; 1.1022x over previous
#include <cuda_runtime.h>
#include <cuda_fp16.h>
#include <cstdint>

// ---------------- problem constants ----------------
static constexpr int E_  = 8;
static constexpr int H_  = 1024;
static constexpr int F_  = 4096;
static constexpr int T_  = 16384;
static constexpr int TPE_ = T_ / E_;   // 2048 tokens per expert

// ---------------- GEMM tile config ----------------
static constexpr int MT = 128;     // M tile
static constexpr int NT = 128;     // N tile
static constexpr int KC = 64;      // K chunk (fp16) = one 128B SW128 row-block
static constexpr int A_BYTES = MT * 128;          // 16384
static constexpr int B_BYTES = NT * 128;          // 16384
static constexpr int OFF_A = 0;
static constexpr int OFF_B = A_BYTES;
static constexpr int STAGE_BYTES = A_BYTES + B_BYTES;   // 32768
static constexpr int NSTAGE = 3;
static constexpr int SMEM_TOTAL = NSTAGE * STAGE_BYTES; // 98304 per CTA (2 CTAs/SM)
static constexpr int NTHREADS = 256;   // 8 warps

// ---------------- scratch (static device globals; no allocation) ----------------
__device__ __half g_xq[(size_t)T_ * H_];
__device__ __half g_w1q[(size_t)E_ * F_ * H_];   // transposed: [E][F][H]
__device__ __half g_w2q[(size_t)E_ * H_ * F_];   // transposed: [E][H][F]
__device__ __half g_iq[(size_t)T_ * F_];         // gelu(intermediate), fp16

#define DI __device__ __forceinline__

DI uint32_t smem_u32(const void* p) {
    uint32_t a;
    asm("{ .reg .u64 t; cvta.to.shared.u64 t, %1; cvt.u32.u64 %0, t; }"
        : "=r"(a) : "l"(p));
    return a;
}

DI float gelu_tanh(float x) {  // jax.nn.gelu default (approximate=True)
    float x3 = x * x * x;
    float t = tanhf(0.7978845608028654f * (x + 0.044715f * x3));
    return 0.5f * x * (1.0f + t);
}

// =================== tensor helpers (base ISA) ===================
#define LDSM_X4(r, addr)                                                           \
    asm volatile("ldmatrix.sync.aligned.m8n8.x4.shared.b16 {%0, %1, %2, %3}, [%4];" \
        : "=r"((r)[0]), "=r"((r)[1]), "=r"((r)[2]), "=r"((r)[3]) : "r"(addr))

DI void mma16816(float* c, const uint32_t* a, const uint32_t* b) {
    asm volatile(
        "mma.sync.aligned.m16n8k16.row.col.f32.f16.f16.f32 "
        "{%0, %1, %2, %3}, {%4, %5, %6, %7}, {%8, %9}, {%0, %1, %2, %3};"
        : "+f"(c[0]), "+f"(c[1]), "+f"(c[2]), "+f"(c[3])
        : "r"(a[0]), "r"(a[1]), "r"(a[2]), "r"(a[3]), "r"(b[0]), "r"(b[1]));
}

DI void cpasync16(uint32_t saddr, const void* gptr) {
    asm volatile("cp.async.cg.shared.global [%0], [%1], 16;"
                 :: "r"(saddr), "l"(gptr) : "memory");
}
#define CP_COMMIT() asm volatile("cp.async.commit_group;" ::: "memory")
#define CP_WAIT1()  asm volatile("cp.async.wait_group 1;" ::: "memory")

// async stage loader: A 128x128B + B 128x128B, SW128-swizzled
DI void load_stage_async(uint32_t stg_u,
                         const __half* __restrict__ A, const __half* __restrict__ B,
                         size_t arow0, size_t brow0, int K, size_t kb, int tid) {
#pragma unroll
    for (int v = tid; v < MT * 8; v += NTHREADS) {
        int r = v >> 3, cc = v & 7;
        size_t gb = ((arow0 + r) * (size_t)K + kb) * 2 + (size_t)cc * 16;
        uint32_t so = (uint32_t)(r * 128 + cc * 16);
        so ^= (so >> 3) & 0x70;
        cpasync16(stg_u + OFF_A + so, (const char*)A + gb);
    }
#pragma unroll
    for (int v = tid; v < NT * 8; v += NTHREADS) {
        int r = v >> 3, cc = v & 7;
        size_t gb = ((brow0 + r) * (size_t)K + kb) * 2 + (size_t)cc * 16;
        uint32_t so = (uint32_t)(r * 128 + cc * 16);
        so ^= (so >> 3) & 0x70;
        cpasync16(stg_u + OFF_B + so, (const char*)B + gb);
    }
}

// ---------------- prep kernels ----------------
// fp32 -> fp16 elementwise, vectorized x4
__global__ void k_cvt(const float4* __restrict__ in, __half2* __restrict__ o, int n4) {
    int i = blockIdx.x * blockDim.x + threadIdx.x;
    if (i >= n4) return;
    float4 v = in[i];
    o[2 * i]     = __floats2half2_rn(v.x, v.y);
    o[2 * i + 1] = __floats2half2_rn(v.z, v.w);
}

// per-expert transpose [R,C] -> [C,R] with fp32->fp16 conversion
__global__ void k_transpose_cvt(const float* __restrict__ in, __half* __restrict__ o,
                                int R, int C) {
    __shared__ float tile[32][33];
    size_t base = (size_t)blockIdx.z * R * C;
    int r0 = blockIdx.y * 32, c0 = blockIdx.x * 32;
    int tx = threadIdx.x, ty = threadIdx.y;
#pragma unroll
    for (int i = ty; i < 32; i += 8)
        tile[i][tx] = in[base + (size_t)(r0 + i) * C + c0 + tx];
    __syncthreads();
#pragma unroll
    for (int i = ty; i < 32; i += 8) {
        float v = tile[tx][i];
        size_t oo = base + (size_t)(c0 + i) * R + r0 + tx;
        o[oo] = __float2half_rn(v);
    }
}

// ---------------- grouped fp16 GEMM (single product, fp32 accum) ----------------
// CTA tile 128x128; 8 warps in 2(M)x4(N) grid of 64x32 warp tiles; 2 CTAs/SM.
// A: [E*rowsA_pe, K] K-major fp16.  B: [E*rowsB_pe, K] K-major fp16.
// GELU_SPLIT: apply tanh-gelu, emit fp16 (GEMM1); else emit fp32 (GEMM2).
template <bool GELU_SPLIT>
__global__ void __launch_bounds__(NTHREADS, 2)
k_gemm(const __half* __restrict__ A, const __half* __restrict__ B,
       int K, int rowsA_pe, int rowsB_pe,
       __half* __restrict__ Oh, float* __restrict__ Of, int ldo) {
    extern __shared__ char smem[];
    uint32_t sb = smem_u32(smem);
    int tid = threadIdx.x, wid = tid >> 5, lid = tid & 31;

    size_t arow0 = (size_t)blockIdx.z * rowsA_pe + (size_t)blockIdx.y * MT;
    size_t brow0 = (size_t)blockIdx.z * rowsB_pe + (size_t)blockIdx.x * NT;
    size_t ncol0 = (size_t)blockIdx.x * NT;
    const int NC = K / KC;

    // warp tile: 64(M) x 32(N); mt 0..3 (m16), nt 0..3 (n8), np 0..1 (B n16 pairs)
    int m_off = (wid & 1) * 64;
    int n_off = (wid >> 1) * 32;
    uint32_t xorv = (uint32_t)(lid & 7) << 4;            // SW128 per-row XOR
    uint32_t a_row = (lid & 7) + ((lid >> 3) & 1) * 8;   // ldmatrix row-provider map
    uint32_t a_kx  = (uint32_t)(lid >> 4) * 16;          // k-byte half (0/16)
    uint32_t b_row = (lid & 7) + ((lid >> 4) & 1) * 8;
    uint32_t b_kx  = ((uint32_t)(lid >> 3) & 1) * 16;

    float acc[4][4][4];
#pragma unroll
    for (int mt = 0; mt < 4; ++mt)
#pragma unroll
        for (int nt = 0; nt < 4; ++nt)
#pragma unroll
            for (int r = 0; r < 4; ++r) acc[mt][nt][r] = 0.0f;

    // prologue: stages 0 and 1 in flight
    load_stage_async(sb, A, B, arow0, brow0, K, 0, tid);
    CP_COMMIT();
    if (NC > 1) load_stage_async(sb + STAGE_BYTES, A, B, arow0, brow0, K, KC, tid);
    CP_COMMIT();

    for (int c = 0; c < NC; ++c) {
        CP_WAIT1();          // stage c landed (<=1 younger group pending)
        __syncthreads();     // stage-c visible to all; stage c-1 buffer reusable
        if (c + 2 < NC)
            load_stage_async(sb + ((c + 2) % NSTAGE) * STAGE_BYTES,
                             A, B, arow0, brow0, K, (size_t)(c + 2) * KC, tid);
        CP_COMMIT();         // commit every iter to keep group count stable

        uint32_t stg_u = sb + (c % NSTAGE) * STAGE_BYTES;
#pragma unroll
        for (int ks = 0; ks < KC / 16; ++ks) {
            uint32_t kin = (uint32_t)ks * 32;
            uint32_t av[4][4], bv[4][2];
#pragma unroll
            for (int mt = 0; mt < 4; ++mt) {
                uint32_t r = m_off + mt * 16 + a_row;
                uint32_t addr = stg_u + OFF_A + (r << 7) + ((kin + a_kx) ^ xorv);
                LDSM_X4(av[mt], addr);
            }
#pragma unroll
            for (int np = 0; np < 2; ++np) {
                uint32_t r = n_off + np * 16 + b_row;
                uint32_t addr = stg_u + OFF_B + (r << 7) + ((kin + b_kx) ^ xorv);
                uint32_t t0[4];
                LDSM_X4(t0, addr);
                bv[np * 2][0] = t0[0]; bv[np * 2][1] = t0[1];
                bv[np * 2 + 1][0] = t0[2]; bv[np * 2 + 1][1] = t0[3];
            }
#pragma unroll
            for (int mt = 0; mt < 4; ++mt)
#pragma unroll
                for (int nt = 0; nt < 4; ++nt)
                    mma16816(acc[mt][nt], av[mt], bv[nt]);
        }
    }

    // epilogue: thread holds D[g][2t..2t+1] (c0,c1) and D[g+8][2t..2t+1] (c2,c3)
    int g = lid >> 2, t2 = (lid & 3) * 2;
#pragma unroll
    for (int mt = 0; mt < 4; ++mt) {
#pragma unroll
        for (int nt = 0; nt < 4; ++nt) {
            size_t col = ncol0 + n_off + nt * 8 + t2;
            size_t row0 = arow0 + m_off + mt * 16 + g;
            size_t row1 = row0 + 8;
            float c0 = acc[mt][nt][0], c1 = acc[mt][nt][1];
            float c2 = acc[mt][nt][2], c3 = acc[mt][nt][3];
            if (GELU_SPLIT) {
                __half2 p0 = __floats2half2_rn(gelu_tanh(c0), gelu_tanh(c1));
                __half2 p1 = __floats2half2_rn(gelu_tanh(c2), gelu_tanh(c3));
                *(__half2*)(Oh + row0 * (size_t)ldo + col) = p0;
                *(__half2*)(Oh + row1 * (size_t)ldo + col) = p1;
            } else {
                *(float2*)(Of + row0 * (size_t)ldo + col) = make_float2(c0, c1);
                *(float2*)(Of + row1 * (size_t)ldo + col) = make_float2(c2, c3);
            }
        }
    }
}

// ---------------- launch ----------------
extern "C" void kernel_launch(void* const* d_in, const int* in_sizes, int n_in,
                              void* d_out, int out_size) {
    (void)in_sizes; (void)n_in; (void)out_size;
    const float* x  = (const float*)d_in[0];
    const float* w1 = (const float*)d_in[1];   // [E, H, F]
    const float* w2 = (const float*)d_in[2];   // [E, F, H]
    float* out = (float*)d_out;                // [T, H]

    __half *xq, *w1q, *w2q, *iq;
    cudaGetSymbolAddress((void**)&xq,  g_xq);
    cudaGetSymbolAddress((void**)&w1q, g_w1q);
    cudaGetSymbolAddress((void**)&w2q, g_w2q);
    cudaGetSymbolAddress((void**)&iq,  g_iq);

    // prep: convert x; transpose+convert weights to K-major B operands
    int n4 = T_ * H_ / 4;
    k_cvt<<<(n4 + 255) / 256, 256>>>((const float4*)x, (__half2*)xq, n4);
    dim3 tb(32, 8);
    k_transpose_cvt<<<dim3(F_ / 32, H_ / 32, E_), tb>>>(w1, w1q, H_, F_); // -> [E,F,H]
    k_transpose_cvt<<<dim3(H_ / 32, F_ / 32, E_), tb>>>(w2, w2q, F_, H_); // -> [E,H,F]

    cudaFuncSetAttribute(k_gemm<true>,  cudaFuncAttributeMaxDynamicSharedMemorySize, SMEM_TOTAL);
    cudaFuncSetAttribute(k_gemm<false>, cudaFuncAttributeMaxDynamicSharedMemorySize, SMEM_TOTAL);

    // GEMM1: I = gelu(X @ W1) -> fp16, [T, F]
    k_gemm<true><<<dim3(F_ / NT, TPE_ / MT, E_), NTHREADS, SMEM_TOTAL>>>(
        xq, w1q, H_, TPE_, F_, iq, nullptr, F_);
    // GEMM2: out = I @ W2 -> fp32, [T, H]
    k_gemm<false><<<dim3(H_ / NT, TPE_ / MT, E_), NTHREADS, SMEM_TOTAL>>>(
        iq, w2q, F_, TPE_, H_, nullptr, out, H_);
}

// round 14
// speedup vs baseline: 1.1740x; 1.0651x over previous
#include <cuda_runtime.h>
#include <cuda_fp16.h>
#include <cstdint>

// ---------------- problem constants ----------------
static constexpr int E_  = 8;
static constexpr int H_  = 1024;
static constexpr int F_  = 4096;
static constexpr int T_  = 16384;
static constexpr int TPE_ = T_ / E_;   // 2048 tokens per expert

// ---------------- GEMM tile config ----------------
static constexpr int MT = 128;     // M tile
static constexpr int NT = 128;     // N tile
static constexpr int KC = 64;      // K chunk (fp16) = one 128B SW128 row-block
static constexpr int A_BYTES = MT * 128;          // 16384
static constexpr int B_BYTES = NT * 128;          // 16384
static constexpr int OFF_A = 0;
static constexpr int OFF_B = A_BYTES;
static constexpr int STAGE_BYTES = A_BYTES + B_BYTES;   // 32768
static constexpr int NSTAGE = 3;
static constexpr int SMEM_TOTAL = NSTAGE * STAGE_BYTES; // 98304 per CTA (2 CTAs/SM)
static constexpr int NTHREADS = 256;   // 8 warps

// ---------------- scratch (static device globals; no allocation) ----------------
__device__ __half g_xq[(size_t)T_ * H_];
__device__ __half g_w1q[(size_t)E_ * F_ * H_];   // transposed: [E][F][H]
__device__ __half g_w2q[(size_t)E_ * H_ * F_];   // transposed: [E][H][F]
__device__ __half g_iq[(size_t)T_ * F_];         // gelu(intermediate), fp16

#define DI __device__ __forceinline__

DI uint32_t smem_u32(const void* p) {
    uint32_t a;
    asm("{ .reg .u64 t; cvta.to.shared.u64 t, %1; cvt.u32.u64 %0, t; }"
        : "=r"(a) : "l"(p));
    return a;
}

DI float gelu_tanh(float x) {  // jax.nn.gelu default (approximate=True)
    float x3 = x * x * x;
    float t = tanhf(0.7978845608028654f * (x + 0.044715f * x3));
    return 0.5f * x * (1.0f + t);
}

// =================== tensor helpers (base ISA) ===================
#define LDSM_X4(r, addr)                                                           \
    asm volatile("ldmatrix.sync.aligned.m8n8.x4.shared.b16 {%0, %1, %2, %3}, [%4];" \
        : "=r"((r)[0]), "=r"((r)[1]), "=r"((r)[2]), "=r"((r)[3]) : "r"(addr))

DI void mma16816(float* c, const uint32_t* a, const uint32_t* b) {
    asm volatile(
        "mma.sync.aligned.m16n8k16.row.col.f32.f16.f16.f32 "
        "{%0, %1, %2, %3}, {%4, %5, %6, %7}, {%8, %9}, {%0, %1, %2, %3};"
        : "+f"(c[0]), "+f"(c[1]), "+f"(c[2]), "+f"(c[3])
        : "r"(a[0]), "r"(a[1]), "r"(a[2]), "r"(a[3]), "r"(b[0]), "r"(b[1]));
}

// cp.async with immediate smem offset (reg+imm addressing)
#define CPASYNC16_IMM(saddr, simm, gptr)                                           \
    asm volatile("cp.async.cg.shared.global [%0+" #simm "], [%1], 16;"             \
                 :: "r"(saddr), "l"(gptr) : "memory")

#define CP_COMMIT() asm volatile("cp.async.commit_group;" ::: "memory")
#define CP_WAIT1()  asm volatile("cp.async.wait_group 1;" ::: "memory")

// strength-reduced stage loader: fixed swizzled smem offsets + striding gmem ptrs.
// Each thread: 4 A rows and 4 B rows, 32 rows apart (smem: +4096B, gmem: +rstride).
DI void load_stage(uint32_t dstA, uint32_t dstB,
                   const char* pA, const char* pB, size_t rstride) {
    CPASYNC16_IMM(dstA, 0,     pA);
    CPASYNC16_IMM(dstA, 4096,  pA + rstride);
    CPASYNC16_IMM(dstA, 8192,  pA + 2 * rstride);
    CPASYNC16_IMM(dstA, 12288, pA + 3 * rstride);
    CPASYNC16_IMM(dstB, 0,     pB);
    CPASYNC16_IMM(dstB, 4096,  pB + rstride);
    CPASYNC16_IMM(dstB, 8192,  pB + 2 * rstride);
    CPASYNC16_IMM(dstB, 12288, pB + 3 * rstride);
}

// ---------------- prep kernels ----------------
// fp32 -> fp16 elementwise, vectorized x4
__global__ void k_cvt(const float4* __restrict__ in, __half2* __restrict__ o, int n4) {
    int i = blockIdx.x * blockDim.x + threadIdx.x;
    if (i >= n4) return;
    float4 v = in[i];
    o[2 * i]     = __floats2half2_rn(v.x, v.y);
    o[2 * i + 1] = __floats2half2_rn(v.z, v.w);
}

// per-expert transpose [R,C] -> [C,R] with fp32->fp16 conversion
__global__ void k_transpose_cvt(const float* __restrict__ in, __half* __restrict__ o,
                                int R, int C) {
    __shared__ float tile[32][33];
    size_t base = (size_t)blockIdx.z * R * C;
    int r0 = blockIdx.y * 32, c0 = blockIdx.x * 32;
    int tx = threadIdx.x, ty = threadIdx.y;
#pragma unroll
    for (int i = ty; i < 32; i += 8)
        tile[i][tx] = in[base + (size_t)(r0 + i) * C + c0 + tx];
    __syncthreads();
#pragma unroll
    for (int i = ty; i < 32; i += 8) {
        float v = tile[tx][i];
        size_t oo = base + (size_t)(c0 + i) * R + r0 + tx;
        o[oo] = __float2half_rn(v);
    }
}

// ---------------- grouped fp16 GEMM (single product, fp32 accum) ----------------
// CTA tile 128x128; 8 warps in 2(M)x4(N) grid of 64x32 warp tiles; 2 CTAs/SM.
// A: [E*rowsA_pe, K] K-major fp16.  B: [E*rowsB_pe, K] K-major fp16.
// GELU_SPLIT: apply tanh-gelu, emit fp16 (GEMM1); else emit fp32 (GEMM2).
template <bool GELU_SPLIT>
__global__ void __launch_bounds__(NTHREADS, 2)
k_gemm(const __half* __restrict__ A, const __half* __restrict__ B,
       int K, int rowsA_pe, int rowsB_pe,
       __half* __restrict__ Oh, float* __restrict__ Of, int ldo) {
    extern __shared__ char smem[];
    uint32_t sb = smem_u32(smem);
    int tid = threadIdx.x, wid = tid >> 5, lid = tid & 31;

    size_t arow0 = (size_t)blockIdx.z * rowsA_pe + (size_t)blockIdx.y * MT;
    size_t brow0 = (size_t)blockIdx.z * rowsB_pe + (size_t)blockIdx.x * NT;
    size_t ncol0 = (size_t)blockIdx.x * NT;
    const int NC = K / KC;

    // ---- loader precompute: fixed swizzled smem offsets + gmem base pointers ----
    int lr = tid >> 3, lc = tid & 7;                 // row 0..31, 16B col 0..7
    uint32_t so = (uint32_t)(lr * 128 + lc * 16);
    so ^= (so >> 3) & 0x70;                          // SW128 swizzle (invariant under +32 rows)
    const char* pA = (const char*)A + ((arow0 + lr) * (size_t)K + lc * 8) * 2;
    const char* pB = (const char*)B + ((brow0 + lr) * (size_t)K + lc * 8) * 2;
    size_t rstride = (size_t)32 * K * 2;             // 32-row advance in bytes

    // ---- MMA fragment addressing precompute ----
    // warp tile: 64(M) x 32(N); mt 0..3 (m16), nt 0..3 (n8), np 0..1 (B n16 pairs)
    int m_off = (wid & 1) * 64;
    int n_off = (wid >> 1) * 32;
    uint32_t xorv = (uint32_t)(lid & 7) << 4;
    uint32_t a_row = (lid & 7) + ((lid >> 3) & 1) * 8;
    uint32_t a_kx  = (uint32_t)(lid >> 4) * 16;
    uint32_t b_row = (lid & 7) + ((lid >> 4) & 1) * 8;
    uint32_t b_kx  = ((uint32_t)(lid >> 3) & 1) * 16;
    // (kin + kx) ^ xorv == (kx ^ xorv) ^ kin  (kx bit4, kin bits5-6, disjoint)
    uint32_t aoff0 = OFF_A + ((uint32_t)(m_off + a_row) << 7) + (a_kx ^ xorv);
    uint32_t boff0 = OFF_B + ((uint32_t)(n_off + b_row) << 7) + (b_kx ^ xorv);

    float acc[4][4][4];
#pragma unroll
    for (int mt = 0; mt < 4; ++mt)
#pragma unroll
        for (int nt = 0; nt < 4; ++nt)
#pragma unroll
            for (int r = 0; r < 4; ++r) acc[mt][nt][r] = 0.0f;

    // prologue: stages 0 and 1 in flight
    load_stage(sb + so, sb + OFF_B + so, pA, pB, rstride);
    CP_COMMIT();
    pA += 128; pB += 128;
    load_stage(sb + STAGE_BYTES + so, sb + STAGE_BYTES + OFF_B + so, pA, pB, rstride);
    CP_COMMIT();
    pA += 128; pB += 128;

    for (int c = 0; c < NC; ++c) {
        CP_WAIT1();          // stage c landed (<=1 younger group pending)
        __syncthreads();     // stage-c visible to all; stage c-1 buffer reusable
        if (c + 2 < NC) {
            uint32_t ld = sb + ((c + 2) % NSTAGE) * STAGE_BYTES;
            load_stage(ld + so, ld + OFF_B + so, pA, pB, rstride);
            pA += 128; pB += 128;
        }
        CP_COMMIT();         // commit every iter to keep group count stable

        uint32_t stg_u = sb + (c % NSTAGE) * STAGE_BYTES;
#pragma unroll
        for (int ks = 0; ks < KC / 16; ++ks) {
            uint32_t kin = (uint32_t)ks * 32;
            uint32_t av[4][4], bv[4][2];
            uint32_t abase = stg_u + (aoff0 ^ kin);
            uint32_t bbase = stg_u + (boff0 ^ kin);
#pragma unroll
            for (int mt = 0; mt < 4; ++mt)
                LDSM_X4(av[mt], abase + mt * 2048);
#pragma unroll
            for (int np = 0; np < 2; ++np) {
                uint32_t t0[4];
                LDSM_X4(t0, bbase + np * 2048);
                bv[np * 2][0] = t0[0]; bv[np * 2][1] = t0[1];
                bv[np * 2 + 1][0] = t0[2]; bv[np * 2 + 1][1] = t0[3];
            }
#pragma unroll
            for (int mt = 0; mt < 4; ++mt)
#pragma unroll
                for (int nt = 0; nt < 4; ++nt)
                    mma16816(acc[mt][nt], av[mt], bv[nt]);
        }
    }

    // epilogue: thread holds D[g][2t..2t+1] (c0,c1) and D[g+8][2t..2t+1] (c2,c3)
    int g = lid >> 2, t2 = (lid & 3) * 2;
#pragma unroll
    for (int mt = 0; mt < 4; ++mt) {
#pragma unroll
        for (int nt = 0; nt < 4; ++nt) {
            size_t col = ncol0 + n_off + nt * 8 + t2;
            size_t row0 = arow0 + m_off + mt * 16 + g;
            size_t row1 = row0 + 8;
            float c0 = acc[mt][nt][0], c1 = acc[mt][nt][1];
            float c2 = acc[mt][nt][2], c3 = acc[mt][nt][3];
            if (GELU_SPLIT) {
                __half2 p0 = __floats2half2_rn(gelu_tanh(c0), gelu_tanh(c1));
                __half2 p1 = __floats2half2_rn(gelu_tanh(c2), gelu_tanh(c3));
                *(__half2*)(Oh + row0 * (size_t)ldo + col) = p0;
                *(__half2*)(Oh + row1 * (size_t)ldo + col) = p1;
            } else {
                *(float2*)(Of + row0 * (size_t)ldo + col) = make_float2(c0, c1);
                *(float2*)(Of + row1 * (size_t)ldo + col) = make_float2(c2, c3);
            }
        }
    }
}

// ---------------- launch ----------------
extern "C" void kernel_launch(void* const* d_in, const int* in_sizes, int n_in,
                              void* d_out, int out_size) {
    (void)in_sizes; (void)n_in; (void)out_size;
    const float* x  = (const float*)d_in[0];
    const float* w1 = (const float*)d_in[1];   // [E, H, F]
    const float* w2 = (const float*)d_in[2];   // [E, F, H]
    float* out = (float*)d_out;                // [T, H]

    __half *xq, *w1q, *w2q, *iq;
    cudaGetSymbolAddress((void**)&xq,  g_xq);
    cudaGetSymbolAddress((void**)&w1q, g_w1q);
    cudaGetSymbolAddress((void**)&w2q, g_w2q);
    cudaGetSymbolAddress((void**)&iq,  g_iq);

    // prep: convert x; transpose+convert weights to K-major B operands
    int n4 = T_ * H_ / 4;
    k_cvt<<<(n4 + 255) / 256, 256>>>((const float4*)x, (__half2*)xq, n4);
    dim3 tb(32, 8);
    k_transpose_cvt<<<dim3(F_ / 32, H_ / 32, E_), tb>>>(w1, w1q, H_, F_); // -> [E,F,H]
    k_transpose_cvt<<<dim3(H_ / 32, F_ / 32, E_), tb>>>(w2, w2q, F_, H_); // -> [E,H,F]

    cudaFuncSetAttribute(k_gemm<true>,  cudaFuncAttributeMaxDynamicSharedMemorySize, SMEM_TOTAL);
    cudaFuncSetAttribute(k_gemm<false>, cudaFuncAttributeMaxDynamicSharedMemorySize, SMEM_TOTAL);

    // GEMM1: I = gelu(X @ W1) -> fp16, [T, F]
    k_gemm<true><<<dim3(F_ / NT, TPE_ / MT, E_), NTHREADS, SMEM_TOTAL>>>(
        xq, w1q, H_, TPE_, F_, iq, nullptr, F_);
    // GEMM2: out = I @ W2 -> fp32, [T, H]
    k_gemm<false><<<dim3(H_ / NT, TPE_ / MT, E_), NTHREADS, SMEM_TOTAL>>>(
        iq, w2q, F_, TPE_, H_, nullptr, out, H_);
}